// round 14
// baseline (speedup 1.0000x reference)
#include <cuda_runtime.h>
#include <cuda_fp16.h>
#include <cstdint>

#define RESP 32
#define RESF 64
#define NP   8192
#define NF   65536
#define CH   128
#define EPSV 1e-5f

// ---- scratch (device globals: allocation-free rule) ----
__device__ int    g_pg[RESP*RESP*RESP];
__device__ __half g_h1[NP*CH];
__device__ __half g_o1h[NF*CH];      // conv1 output, fp16
__device__ __half g_h2[NF*CH];
__device__ __half g_M1h[64*CH*CH];   // aggregated conv1 weights, [mat][n][k], fp16
__device__ __half g_W2h[27*CH*CH];   // conv2 weights, [mat][n][k], fp16
__device__ float  g_sum[32], g_sq[32];   // GN2 stats (accumulated by conv1 epilogue)

// ================= helpers =================
__device__ __forceinline__ uint32_t smem_u32(const void* p) {
    uint32_t a;
    asm("{ .reg .u64 t; cvta.to.shared.u64 t, %1; cvt.u32.u64 %0, t; }" : "=r"(a) : "l"(p));
    return a;
}
__device__ __forceinline__ void cp16(uint32_t dst, const void* src, uint32_t ssz) {
    asm volatile("cp.async.cg.shared.global [%0], [%1], 16, %2;" :: "r"(dst), "l"(src), "r"(ssz));
}
__device__ __forceinline__ void cp_commit() { asm volatile("cp.async.commit_group;"); }
#define CP_WAIT(n) asm volatile("cp.async.wait_group %0;" :: "n"(n) : "memory")

__device__ __forceinline__ void ldsm4(uint32_t* r, uint32_t addr) {
    asm volatile("ldmatrix.sync.aligned.m8n8.x4.shared.b16 {%0,%1,%2,%3}, [%4];"
        : "=r"(r[0]), "=r"(r[1]), "=r"(r[2]), "=r"(r[3]) : "r"(addr));
}
// m16n8k16 fp16 MMA, fp32 accumulate
__device__ __forceinline__ void mma_f16(float* d, const uint32_t* a, const uint32_t* b) {
    asm volatile("mma.sync.aligned.m16n8k16.row.col.f32.f16.f16.f32 "
        "{%0,%1,%2,%3}, {%4,%5,%6,%7}, {%8,%9}, {%0,%1,%2,%3};"
        : "+f"(d[0]), "+f"(d[1]), "+f"(d[2]), "+f"(d[3])
        : "r"(a[0]), "r"(a[1]), "r"(a[2]), "r"(a[3]), "r"(b[0]), "r"(b[1]));
}
__device__ __forceinline__ void store_h4(__half* dst, float x, float y, float z, float w) {
    __half2 p0 = __floats2half2_rn(x, y);
    __half2 p1 = __floats2half2_rn(z, w);
    uint2 u;
    u.x = *reinterpret_cast<uint32_t*>(&p0);
    u.y = *reinterpret_cast<uint32_t*>(&p1);
    *reinterpret_cast<uint2*>(dst) = u;
}
__device__ __forceinline__ void store_h2(__half* dst, float x, float y) {
    __half2 p = __floats2half2_rn(x, y);
    *reinterpret_cast<uint32_t*>(dst) = *reinterpret_cast<uint32_t*>(&p);
}

// ================= fused grid build + stat zeroing =================
__global__ __launch_bounds__(1024)
void k_grid(const int* __restrict__ coords) {
    int t = threadIdx.x;
    for (int i = t; i < RESP*RESP*RESP; i += 1024) g_pg[i] = -1;
    if (t < 32) { g_sum[t] = 0.f; g_sq[t] = 0.f; }
    __syncthreads();
    for (int i = t; i < NP; i += 1024)
        g_pg[(coords[i*3]*RESP + coords[i*3+1])*RESP + coords[i*3+2]] = i;
}

// ================= fused weight prep (fp16 output, [mat][n][k]) =================
__global__ void k_prepw(const float* __restrict__ W1, const float* __restrict__ W2) {
    int idx = blockIdx.x * blockDim.x + threadIdx.x;
    if (idx < 64*CH*CH) {
        int m = idx >> 14, rest = idx & 16383;
        int n = rest >> 7, kk = rest & 127;
        int k = m >> 3, j = m & 7;
        int s[3], cnt[3];
#pragma unroll
        for (int a = 0; a < 3; a++) {
            int o  = (k >> (2 - a)) & 1;
            int eb = (j >> (2 - a)) & 1;
            cnt[a] = 1 + (o ^ eb);
            s[a]   = -1 + eb * (1 + o);
        }
        float acc = 0.f;
        for (int d0 = 0; d0 < cnt[0]; d0++)
            for (int d1 = 0; d1 < cnt[1]; d1++)
                for (int d2 = 0; d2 < cnt[2]; d2++) {
                    int k27 = ((s[0]+d0+1)*3 + (s[1]+d1+1))*3 + (s[2]+d2+1);
                    acc += W1[k27*CH*CH + kk*CH + n];
                }
        g_M1h[idx] = __float2half_rn(acc);
    } else if (idx < 91*CH*CH) {
        int i2 = idx - 64*CH*CH;
        int m = i2 >> 14, rest = i2 & 16383;
        int n = rest >> 7, kk = rest & 127;
        g_W2h[i2] = __float2half_rn(W2[m*CH*CH + kk*CH + n]);
    }
}

// ================= GN1: fused stats + normalize + SiLU -> fp16 =================
__global__ __launch_bounds__(256)
void k_gn1(const float* __restrict__ feats,
           const float* __restrict__ gamma, const float* __restrict__ beta) {
    int g = blockIdx.x, t = threadIdx.x;
    float s = 0.f, q = 0.f;
    for (int r = t; r < NP; r += 256) {
        float4 v = *reinterpret_cast<const float4*>(feats + r*CH + g*4);
        s += (v.x + v.y) + (v.z + v.w);
        q += (v.x*v.x + v.y*v.y) + (v.z*v.z + v.w*v.w);
    }
    __shared__ float ss[256], sq[256];
    ss[t] = s; sq[t] = q;
    __syncthreads();
    for (int st = 128; st > 0; st >>= 1) {
        if (t < st) { ss[t] += ss[t+st]; sq[t] += sq[t+st]; }
        __syncthreads();
    }
    const float invcnt = 1.f / (NP * 4);
    float mean = ss[0] * invcnt;
    float var  = sq[0] * invcnt - mean * mean;
    float inv  = rsqrtf(var + EPSV);
    float4 ga = *reinterpret_cast<const float4*>(gamma + g*4);
    float4 be = *reinterpret_cast<const float4*>(beta + g*4);
    for (int r = t; r < NP; r += 256) {
        float4 v = *reinterpret_cast<const float4*>(feats + r*CH + g*4);
        float y, ox, oy, oz, ow;
        y = (v.x - mean)*inv*ga.x + be.x; ox = y / (1.f + expf(-y));
        y = (v.y - mean)*inv*ga.y + be.y; oy = y / (1.f + expf(-y));
        y = (v.z - mean)*inv*ga.z + be.z; oz = y / (1.f + expf(-y));
        y = (v.w - mean)*inv*ga.w + be.w; ow = y / (1.f + expf(-y));
        store_h4(g_h1 + r*CH + g*4, ox, oy, oz, ow);
    }
}

// ================= GN2 normalize + SiLU (stats from conv1 epilogue) =================
__global__ void k_gnsilu2(const float* __restrict__ gamma, const float* __restrict__ beta) {
    int idx = blockIdx.x * blockDim.x + threadIdx.x;
    if (idx >= NF*32) return;
    int g = idx & 31;
    const float invcnt = 1.f / (NF * 4);
    float mean = g_sum[g] * invcnt;
    float var  = g_sq[g] * invcnt - mean * mean;
    float inv  = rsqrtf(var + EPSV);
    uint2 u = *reinterpret_cast<const uint2*>(g_o1h + idx*4);
    __half2 h0 = *reinterpret_cast<__half2*>(&u.x);
    __half2 h1 = *reinterpret_cast<__half2*>(&u.y);
    float2 v0 = __half22float2(h0);
    float2 v1 = __half22float2(h1);
    float4 ga = reinterpret_cast<const float4*>(gamma)[g];
    float4 be = reinterpret_cast<const float4*>(beta)[g];
    float y, ox, oy, oz, ow;
    y = (v0.x - mean)*inv*ga.x + be.x; ox = y / (1.f + expf(-y));
    y = (v0.y - mean)*inv*ga.y + be.y; oy = y / (1.f + expf(-y));
    y = (v1.x - mean)*inv*ga.z + be.z; oz = y / (1.f + expf(-y));
    y = (v1.y - mean)*inv*ga.w + be.w; ow = y / (1.f + expf(-y));
    store_h4(g_h2 + idx*4, ox, oy, oz, ow);
}

// ================= fp16 mma conv kernels =================
// CTA 64 rows x 128 cols, 8 warps (2m x 4n), warp tile 32x32 -> acc=32 regs.
// BK=64 fp16 per stage; stage = A 8KB + B 16KB = 24KB. PD-stage cp.async.
// conv1 (ISC2=0): MB=2 (regs grow with fused GN2 stats); conv2: MB=3.
#define STG_SZ 24576
#define TM 64

template<int NTAPS, int PD, bool ISC2, int MB>
__global__ __launch_bounds__(256, MB)
void k_convmma(const int* __restrict__ coords, const float* __restrict__ bias,
               const float* __restrict__ feats, float* __restrict__ dout) {
    extern __shared__ char dsm[];
    uint32_t smS = smem_u32(dsm);
    int* snb = (int*)(dsm + PD*STG_SZ);

    const __half* hsrc = ISC2 ? g_h2  : g_h1;
    const __half* Wp   = ISC2 ? g_W2h : g_M1h;

    int tid = threadIdx.x, lane = tid & 31, wid = tid >> 5;
    int wm = wid >> 2, wn = wid & 3;          // 2m x 4n
    int bx = blockIdx.x, ko = blockIdx.y;
    const int matBase = ISC2 ? 0 : ko*8;

    // ---- neighbor precompute (TM=64 rows) ----
    for (int t = tid; t < NTAPS*TM; t += 256) {
        int tap = t >> 6, row = t & (TM-1);
        int nb = -1;
        if (ISC2) {
            int grow = bx*TM + row;
            int pi = grow >> 3, k8 = grow & 7;
            int f0 = 2*coords[pi*3+0] + ((k8 >> 2) & 1) + (tap/9 - 1);
            int f1 = 2*coords[pi*3+1] + ((k8 >> 1) & 1) + ((tap/3) % 3 - 1);
            int f2 = 2*coords[pi*3+2] + (k8 & 1)        + (tap % 3 - 1);
            if ((unsigned)f0 < RESF && (unsigned)f1 < RESF && (unsigned)f2 < RESF) {
                int p = g_pg[((f0 >> 1)*RESP + (f1 >> 1))*RESP + (f2 >> 1)];
                if (p >= 0) nb = p*8 + (((f0 & 1) << 2) | ((f1 & 1) << 1) | (f2 & 1));
            }
        } else {
            int p = bx*TM + row;
            int q0 = coords[p*3+0] + ((ko >> 2) & 1) - 1 + ((tap >> 2) & 1);
            int q1 = coords[p*3+1] + ((ko >> 1) & 1) - 1 + ((tap >> 1) & 1);
            int q2 = coords[p*3+2] + (ko & 1)        - 1 + (tap & 1);
            if ((unsigned)q0 < RESP && (unsigned)q1 < RESP && (unsigned)q2 < RESP)
                nb = g_pg[(q0*RESP + q1)*RESP + q2];
        }
        snb[t] = nb;
    }
    __syncthreads();

    // loaders: A 64 rows -> 4 threads/row, 2 cp16 each; B 128 rows -> 2 threads/row, 4 cp16 each
    const int ar = tid >> 2, ac0 = (tid & 3) * 2, arx = ar & 7;
    const int br = tid >> 1, bh = tid & 1,       brx = br & 7;

    // ldsm lane constants (m16n8k16 fragment mapping)
    const int laneAr = (lane & 7) + ((lane >> 3) & 1)*8;
    const int laneAc = (lane >> 4) & 1;
    const int laneBr = (lane & 7) + ((lane >> 4) & 1)*8;
    const int laneBc = (lane >> 3) & 1;
    uint32_t offA[2], offB[2]; int rxA[2], rxB[2];
#pragma unroll
    for (int i = 0; i < 2; i++) {
        int rA = wm*32 + i*16 + laneAr;
        offA[i] = (uint32_t)rA * 128u; rxA[i] = rA & 7;
        int rB = wn*32 + i*16 + laneBr;
        offB[i] = 8192u + (uint32_t)rB * 128u; rxB[i] = rB & 7;
    }

    float acc[2][4][4];
#pragma unroll
    for (int mt = 0; mt < 2; mt++)
#pragma unroll
        for (int nt = 0; nt < 4; nt++)
#pragma unroll
            for (int c = 0; c < 4; c++) acc[mt][nt][c] = 0.f;

    const int T = NTAPS * 2;   // BK=64: 2 stages per tap

#define LOAD_STAGE(S, BUF) do { \
        int tap_ = (S) >> 1, c0_ = ((S) & 1) * 64; \
        uint32_t base_ = smS + (BUF)*STG_SZ; \
        { \
            int src_ = snb[tap_*TM + ar]; \
            uint32_t ssz_ = src_ >= 0 ? 16u : 0u; \
            const __half* ap_ = hsrc + (src_ < 0 ? 0 : src_)*CH + c0_; \
            uint32_t ad_ = base_ + (uint32_t)ar*128u; \
            _Pragma("unroll") \
            for (int i_ = 0; i_ < 2; i_++) { \
                int c_ = ac0 + i_; \
                cp16(ad_ + (uint32_t)((c_ ^ arx) << 4), ap_ + c_*8, ssz_); \
            } \
        } \
        { \
            const __half* bp_ = Wp + ((matBase + tap_)*128 + br)*128 + c0_; \
            uint32_t bd_ = base_ + 8192u + (uint32_t)br*128u; \
            _Pragma("unroll") \
            for (int i_ = 0; i_ < 4; i_++) { \
                int c_ = bh*4 + i_; \
                cp16(bd_ + (uint32_t)((c_ ^ brx) << 4), bp_ + c_*8, 16u); \
            } \
        } \
        cp_commit(); \
    } while (0)

    // prologue: stages 0..PD-2
#pragma unroll
    for (int s = 0; s < PD - 1; s++) LOAD_STAGE(s, s);

    int sbuf = 0;
    for (int s = 0; s < T; s++) {
        if (s + PD - 1 < T) CP_WAIT(PD - 2); else CP_WAIT(0);
        __syncthreads();
        if (s + PD - 1 < T) {
            int bufn = sbuf + PD - 1; if (bufn >= PD) bufn -= PD;
            LOAD_STAGE(s + PD - 1, bufn);
        }
        uint32_t stg = smS + (uint32_t)sbuf*STG_SZ;
#pragma unroll
        for (int ks = 0; ks < 4; ks++) {
            int cA = ks*2 + laneAc, cB = ks*2 + laneBc;
            uint32_t a[2][4], b[2][4];
            ldsm4(a[0], stg + offA[0] + (uint32_t)((cA ^ rxA[0]) << 4));
            ldsm4(a[1], stg + offA[1] + (uint32_t)((cA ^ rxA[1]) << 4));
            ldsm4(b[0], stg + offB[0] + (uint32_t)((cB ^ rxB[0]) << 4));
            ldsm4(b[1], stg + offB[1] + (uint32_t)((cB ^ rxB[1]) << 4));
#pragma unroll
            for (int mt = 0; mt < 2; mt++)
#pragma unroll
                for (int nt = 0; nt < 4; nt++)
                    mma_f16(acc[mt][nt], a[mt], &b[nt >> 1][(nt & 1)*2]);
        }
        sbuf++; if (sbuf == PD) sbuf = 0;
    }
#undef LOAD_STAGE

    // ---- epilogue ----
    float* sred = (float*)dsm;      // reuse stage smem for GN2 stat reduction
    if (!ISC2) {
        __syncthreads();
        if (tid < 64) sred[tid] = 0.f;
        __syncthreads();
    }

    // per-nt group partials: group(nt) = wn*8 + nt*2 + ((lane&3)>>1)
    float gs[4], gq[4];
#pragma unroll
    for (int nt = 0; nt < 4; nt++) { gs[nt] = 0.f; gq[nt] = 0.f; }

#pragma unroll
    for (int mt = 0; mt < 2; mt++) {
        int rl = wm*32 + mt*16 + (lane >> 2);
#pragma unroll
        for (int half = 0; half < 2; half++) {
            int row = rl + half*8;
            int orow, prow;
            if (ISC2) { orow = bx*TM + row; prow = orow >> 3; }
            else      { orow = (bx*TM + row)*8 + ko; prow = -1; }
#pragma unroll
            for (int nt = 0; nt < 4; nt++) {
                int col = wn*32 + nt*8 + (lane & 3)*2;
                float2 bb = *reinterpret_cast<const float2*>(bias + col);
                float vx = acc[mt][nt][half*2 + 0] + bb.x;
                float vy = acc[mt][nt][half*2 + 1] + bb.y;
                if (ISC2) {
                    float2 rr = *reinterpret_cast<const float2*>(feats + prow*CH + col);
                    vx += rr.x; vy += rr.y;
                    float2 o; o.x = vx; o.y = vy;
                    *reinterpret_cast<float2*>(dout + orow*CH + col) = o;
                } else {
                    gs[nt] += vx + vy;
                    gq[nt] += vx*vx + vy*vy;
                    store_h2(g_o1h + orow*CH + col, vx, vy);
                }
            }
        }
    }

    if (!ISC2) {
#pragma unroll
        for (int nt = 0; nt < 4; nt++) {
            int g = wn*8 + nt*2 + ((lane & 3) >> 1);
            atomicAdd(&sred[g], gs[nt]);
            atomicAdd(&sred[32 + g], gq[nt]);
        }
        __syncthreads();
        if (tid < 32) {
            atomicAdd(&g_sum[tid], sred[tid]);
            atomicAdd(&g_sq[tid], sred[32 + tid]);
        }
    }
}

// ================= launch =================
extern "C" void kernel_launch(void* const* d_in, const int* in_sizes, int n_in,
                              void* d_out, int out_size) {
    const float* feats  = (const float*)d_in[0];
    const float* gamma1 = (const float*)d_in[1];
    const float* beta1  = (const float*)d_in[2];
    const float* W1     = (const float*)d_in[3];
    const float* b1     = (const float*)d_in[4];
    const float* gamma2 = (const float*)d_in[5];
    const float* beta2  = (const float*)d_in[6];
    const float* W2     = (const float*)d_in[7];
    const float* b2     = (const float*)d_in[8];
    const int*   coords = (const int*)d_in[9];
    float* out = (float*)d_out;

    const int smem1 = 3*STG_SZ + 8*TM*4;     // 75776  (PD=3)
    const int smem2 = 2*STG_SZ + 27*TM*4;    // 56064  (PD=2)
    cudaFuncSetAttribute(k_convmma<8,3,false,2>, cudaFuncAttributeMaxDynamicSharedMemorySize, smem1);
    cudaFuncSetAttribute(k_convmma<27,2,true,3>, cudaFuncAttributeMaxDynamicSharedMemorySize, smem2);

    // (0) grid build + GN2 stat zeroing
    k_grid<<<1, 1024>>>(coords);
    // (1) weight prep -> fp16 [mat][n][k]
    k_prepw<<<(91*CH*CH + 255)/256, 256>>>(W1, W2);
    // (2) GN1 fused stats+norm+SiLU -> g_h1 (fp16)
    k_gn1<<<32, 256>>>(feats, gamma1, beta1);
    // (3) conv1 -> g_o1h (fp16) + GN2 stats via atomics   [ncu-profiled slot]
    k_convmma<8,3,false,2><<<dim3(NP/TM, 8), 256, smem1>>>(coords, b1, nullptr, nullptr);
    // (4) GN2 normalize + SiLU -> g_h2 (fp16)
    k_gnsilu2<<<(NF*32 + 255)/256, 256>>>(gamma2, beta2);
    // (5) conv2 (fine-level, 27 taps) + bias + residual -> out
    k_convmma<27,2,true,3><<<NF/TM, 256, smem2>>>(coords, b2, feats, out);
}

// round 15
// speedup vs baseline: 1.1101x; 1.1101x over previous
#include <cuda_runtime.h>
#include <cuda_fp16.h>
#include <cstdint>

#define RESP 32
#define RESF 64
#define NP   8192
#define NF   65536
#define CH   128
#define EPSV 1e-5f

// ---- scratch (device globals: allocation-free rule) ----
__device__ int    g_pg[RESP*RESP*RESP];
__device__ __half g_h1[NP*CH];
__device__ __half g_o1h[NF*CH];      // conv1 output, fp16
__device__ __half g_h2[NF*CH];
__device__ __half g_M1h[64*CH*CH];   // aggregated conv1 weights, [mat][n][k], fp16
__device__ __half g_W2h[27*CH*CH];   // conv2 weights, [mat][n][k], fp16
__device__ float  g_sum[32], g_sq[32];      // GN2 stats
__device__ float  g_ps[32][32], g_pq[32][32];

// ================= helpers =================
__device__ __forceinline__ uint32_t smem_u32(const void* p) {
    uint32_t a;
    asm("{ .reg .u64 t; cvta.to.shared.u64 t, %1; cvt.u32.u64 %0, t; }" : "=r"(a) : "l"(p));
    return a;
}
__device__ __forceinline__ void cp16(uint32_t dst, const void* src, uint32_t ssz) {
    asm volatile("cp.async.cg.shared.global [%0], [%1], 16, %2;" :: "r"(dst), "l"(src), "r"(ssz));
}
__device__ __forceinline__ void cp_commit() { asm volatile("cp.async.commit_group;"); }
#define CP_WAIT(n) asm volatile("cp.async.wait_group %0;" :: "n"(n) : "memory")

__device__ __forceinline__ void ldsm4(uint32_t* r, uint32_t addr) {
    asm volatile("ldmatrix.sync.aligned.m8n8.x4.shared.b16 {%0,%1,%2,%3}, [%4];"
        : "=r"(r[0]), "=r"(r[1]), "=r"(r[2]), "=r"(r[3]) : "r"(addr));
}
// m16n8k16 fp16 MMA, fp32 accumulate
__device__ __forceinline__ void mma_f16(float* d, const uint32_t* a, const uint32_t* b) {
    asm volatile("mma.sync.aligned.m16n8k16.row.col.f32.f16.f16.f32 "
        "{%0,%1,%2,%3}, {%4,%5,%6,%7}, {%8,%9}, {%0,%1,%2,%3};"
        : "+f"(d[0]), "+f"(d[1]), "+f"(d[2]), "+f"(d[3])
        : "r"(a[0]), "r"(a[1]), "r"(a[2]), "r"(a[3]), "r"(b[0]), "r"(b[1]));
}
__device__ __forceinline__ void store_h4(__half* dst, float x, float y, float z, float w) {
    __half2 p0 = __floats2half2_rn(x, y);
    __half2 p1 = __floats2half2_rn(z, w);
    uint2 u;
    u.x = *reinterpret_cast<uint32_t*>(&p0);
    u.y = *reinterpret_cast<uint32_t*>(&p1);
    *reinterpret_cast<uint2*>(dst) = u;
}
__device__ __forceinline__ void store_h2(__half* dst, float x, float y) {
    __half2 p = __floats2half2_rn(x, y);
    *reinterpret_cast<uint32_t*>(dst) = *reinterpret_cast<uint32_t*>(&p);
}

// ================= fused grid build =================
__global__ __launch_bounds__(1024)
void k_grid(const int* __restrict__ coords) {
    int t = threadIdx.x;
    for (int i = t; i < RESP*RESP*RESP; i += 1024) g_pg[i] = -1;
    __syncthreads();
    for (int i = t; i < NP; i += 1024)
        g_pg[(coords[i*3]*RESP + coords[i*3+1])*RESP + coords[i*3+2]] = i;
}

// ================= fused weight prep (fp16 output, [mat][n][k]) =================
__global__ void k_prepw(const float* __restrict__ W1, const float* __restrict__ W2) {
    int idx = blockIdx.x * blockDim.x + threadIdx.x;
    if (idx < 64*CH*CH) {
        int m = idx >> 14, rest = idx & 16383;
        int n = rest >> 7, kk = rest & 127;
        int k = m >> 3, j = m & 7;
        int s[3], cnt[3];
#pragma unroll
        for (int a = 0; a < 3; a++) {
            int o  = (k >> (2 - a)) & 1;
            int eb = (j >> (2 - a)) & 1;
            cnt[a] = 1 + (o ^ eb);
            s[a]   = -1 + eb * (1 + o);
        }
        float acc = 0.f;
        for (int d0 = 0; d0 < cnt[0]; d0++)
            for (int d1 = 0; d1 < cnt[1]; d1++)
                for (int d2 = 0; d2 < cnt[2]; d2++) {
                    int k27 = ((s[0]+d0+1)*3 + (s[1]+d1+1))*3 + (s[2]+d2+1);
                    acc += W1[k27*CH*CH + kk*CH + n];
                }
        g_M1h[idx] = __float2half_rn(acc);
    } else if (idx < 91*CH*CH) {
        int i2 = idx - 64*CH*CH;
        int m = i2 >> 14, rest = i2 & 16383;
        int n = rest >> 7, kk = rest & 127;
        g_W2h[i2] = __float2half_rn(W2[m*CH*CH + kk*CH + n]);
    }
}

// ================= GN1: fused stats + normalize + SiLU -> fp16 =================
__global__ __launch_bounds__(256)
void k_gn1(const float* __restrict__ feats,
           const float* __restrict__ gamma, const float* __restrict__ beta) {
    int g = blockIdx.x, t = threadIdx.x;
    float s = 0.f, q = 0.f;
    for (int r = t; r < NP; r += 256) {
        float4 v = *reinterpret_cast<const float4*>(feats + r*CH + g*4);
        s += (v.x + v.y) + (v.z + v.w);
        q += (v.x*v.x + v.y*v.y) + (v.z*v.z + v.w*v.w);
    }
    __shared__ float ss[256], sq[256];
    ss[t] = s; sq[t] = q;
    __syncthreads();
    for (int st = 128; st > 0; st >>= 1) {
        if (t < st) { ss[t] += ss[t+st]; sq[t] += sq[t+st]; }
        __syncthreads();
    }
    const float invcnt = 1.f / (NP * 4);
    float mean = ss[0] * invcnt;
    float var  = sq[0] * invcnt - mean * mean;
    float inv  = rsqrtf(var + EPSV);
    float4 ga = *reinterpret_cast<const float4*>(gamma + g*4);
    float4 be = *reinterpret_cast<const float4*>(beta + g*4);
    for (int r = t; r < NP; r += 256) {
        float4 v = *reinterpret_cast<const float4*>(feats + r*CH + g*4);
        float y, ox, oy, oz, ow;
        y = (v.x - mean)*inv*ga.x + be.x; ox = y / (1.f + expf(-y));
        y = (v.y - mean)*inv*ga.y + be.y; oy = y / (1.f + expf(-y));
        y = (v.z - mean)*inv*ga.z + be.z; oz = y / (1.f + expf(-y));
        y = (v.w - mean)*inv*ga.w + be.w; ow = y / (1.f + expf(-y));
        store_h4(g_h1 + r*CH + g*4, ox, oy, oz, ow);
    }
}

// ================= GN2 stats (two-phase over fp16 g_o1h) =================
__global__ void k_stats1(int nsl) {
    int g = blockIdx.x, sl = blockIdx.y;
    int per = NF / nsl, r0 = sl * per;
    float s = 0.f, q = 0.f;
    for (int r = r0 + threadIdx.x; r < r0 + per; r += blockDim.x) {
        uint2 u = *reinterpret_cast<const uint2*>(g_o1h + r*CH + g*4);
        float2 v0 = __half22float2(*reinterpret_cast<__half2*>(&u.x));
        float2 v1 = __half22float2(*reinterpret_cast<__half2*>(&u.y));
        s += (v0.x + v0.y) + (v1.x + v1.y);
        q += (v0.x*v0.x + v0.y*v0.y) + (v1.x*v1.x + v1.y*v1.y);
    }
    __shared__ float ss[256], sq[256];
    ss[threadIdx.x] = s; sq[threadIdx.x] = q;
    __syncthreads();
    for (int st = 128; st > 0; st >>= 1) {
        if (threadIdx.x < st) { ss[threadIdx.x] += ss[threadIdx.x+st]; sq[threadIdx.x] += sq[threadIdx.x+st]; }
        __syncthreads();
    }
    if (threadIdx.x == 0) { g_ps[g][sl] = ss[0]; g_pq[g][sl] = sq[0]; }
}
__global__ void k_stats2(int nsl) {
    int g = blockIdx.x, t = threadIdx.x;
    float s = (t < nsl) ? g_ps[g][t] : 0.f;
    float q = (t < nsl) ? g_pq[g][t] : 0.f;
#pragma unroll
    for (int o = 16; o > 0; o >>= 1) {
        s += __shfl_xor_sync(0xffffffff, s, o);
        q += __shfl_xor_sync(0xffffffff, q, o);
    }
    if (t == 0) { g_sum[g] = s; g_sq[g] = q; }
}
__global__ void k_gnsilu2(const float* __restrict__ gamma, const float* __restrict__ beta) {
    int idx = blockIdx.x * blockDim.x + threadIdx.x;
    if (idx >= NF*32) return;
    int g = idx & 31;
    const float invcnt = 1.f / (NF * 4);
    float mean = g_sum[g] * invcnt;
    float var  = g_sq[g] * invcnt - mean * mean;
    float inv  = rsqrtf(var + EPSV);
    uint2 u = *reinterpret_cast<const uint2*>(g_o1h + idx*4);
    float2 v0 = __half22float2(*reinterpret_cast<__half2*>(&u.x));
    float2 v1 = __half22float2(*reinterpret_cast<__half2*>(&u.y));
    float4 ga = reinterpret_cast<const float4*>(gamma)[g];
    float4 be = reinterpret_cast<const float4*>(beta)[g];
    float y, ox, oy, oz, ow;
    y = (v0.x - mean)*inv*ga.x + be.x; ox = y / (1.f + expf(-y));
    y = (v0.y - mean)*inv*ga.y + be.y; oy = y / (1.f + expf(-y));
    y = (v1.x - mean)*inv*ga.z + be.z; oz = y / (1.f + expf(-y));
    y = (v1.y - mean)*inv*ga.w + be.w; ow = y / (1.f + expf(-y));
    store_h4(g_h2 + idx*4, ox, oy, oz, ow);
}

// ================= fp16 mma conv kernels =================
// CTA 64 rows x 128 cols, 8 warps (2m x 4n), warp tile 32x32 -> acc=32 regs.
// BK=64 fp16 per stage; stage = A 8KB + B 16KB = 24KB. PD-stage cp.async.
// __launch_bounds__(256,3): 3 CTAs/SM = 24 warps.
#define STG_SZ 24576
#define TM 64

template<int NTAPS, int PD, bool ISC2>
__global__ __launch_bounds__(256, 3)
void k_convmma(const int* __restrict__ coords, const float* __restrict__ bias,
               const float* __restrict__ feats, float* __restrict__ dout) {
    extern __shared__ char dsm[];
    uint32_t smS = smem_u32(dsm);
    int* snb = (int*)(dsm + PD*STG_SZ);

    const __half* hsrc = ISC2 ? g_h2  : g_h1;
    const __half* Wp   = ISC2 ? g_W2h : g_M1h;

    int tid = threadIdx.x, lane = tid & 31, wid = tid >> 5;
    int wm = wid >> 2, wn = wid & 3;          // 2m x 4n
    int bx = blockIdx.x, ko = blockIdx.y;
    const int matBase = ISC2 ? 0 : ko*8;

    // ---- neighbor precompute (TM=64 rows) ----
    for (int t = tid; t < NTAPS*TM; t += 256) {
        int tap = t >> 6, row = t & (TM-1);
        int nb = -1;
        if (ISC2) {
            int grow = bx*TM + row;
            int pi = grow >> 3, k8 = grow & 7;
            int f0 = 2*coords[pi*3+0] + ((k8 >> 2) & 1) + (tap/9 - 1);
            int f1 = 2*coords[pi*3+1] + ((k8 >> 1) & 1) + ((tap/3) % 3 - 1);
            int f2 = 2*coords[pi*3+2] + (k8 & 1)        + (tap % 3 - 1);
            if ((unsigned)f0 < RESF && (unsigned)f1 < RESF && (unsigned)f2 < RESF) {
                int p = g_pg[((f0 >> 1)*RESP + (f1 >> 1))*RESP + (f2 >> 1)];
                if (p >= 0) nb = p*8 + (((f0 & 1) << 2) | ((f1 & 1) << 1) | (f2 & 1));
            }
        } else {
            int p = bx*TM + row;
            int q0 = coords[p*3+0] + ((ko >> 2) & 1) - 1 + ((tap >> 2) & 1);
            int q1 = coords[p*3+1] + ((ko >> 1) & 1) - 1 + ((tap >> 1) & 1);
            int q2 = coords[p*3+2] + (ko & 1)        - 1 + (tap & 1);
            if ((unsigned)q0 < RESP && (unsigned)q1 < RESP && (unsigned)q2 < RESP)
                nb = g_pg[(q0*RESP + q1)*RESP + q2];
        }
        snb[t] = nb;
    }
    __syncthreads();

    // loaders: A 64 rows -> 4 threads/row, 2 cp16 each; B 128 rows -> 2 threads/row, 4 cp16 each
    const int ar = tid >> 2, ac0 = (tid & 3) * 2, arx = ar & 7;
    const int br = tid >> 1, bh = tid & 1,       brx = br & 7;

    // ldsm lane constants (m16n8k16 fragment mapping)
    const int laneAr = (lane & 7) + ((lane >> 3) & 1)*8;
    const int laneAc = (lane >> 4) & 1;
    const int laneBr = (lane & 7) + ((lane >> 4) & 1)*8;
    const int laneBc = (lane >> 3) & 1;
    uint32_t offA[2], offB[2]; int rxA[2], rxB[2];
#pragma unroll
    for (int i = 0; i < 2; i++) {
        int rA = wm*32 + i*16 + laneAr;
        offA[i] = (uint32_t)rA * 128u; rxA[i] = rA & 7;
        int rB = wn*32 + i*16 + laneBr;
        offB[i] = 8192u + (uint32_t)rB * 128u; rxB[i] = rB & 7;
    }

    float acc[2][4][4];
#pragma unroll
    for (int mt = 0; mt < 2; mt++)
#pragma unroll
        for (int nt = 0; nt < 4; nt++)
#pragma unroll
            for (int c = 0; c < 4; c++) acc[mt][nt][c] = 0.f;

    const int T = NTAPS * 2;   // BK=64: 2 stages per tap

#define LOAD_STAGE(S, BUF) do { \
        int tap_ = (S) >> 1, c0_ = ((S) & 1) * 64; \
        uint32_t base_ = smS + (BUF)*STG_SZ; \
        { \
            int src_ = snb[tap_*TM + ar]; \
            uint32_t ssz_ = src_ >= 0 ? 16u : 0u; \
            const __half* ap_ = hsrc + (src_ < 0 ? 0 : src_)*CH + c0_; \
            uint32_t ad_ = base_ + (uint32_t)ar*128u; \
            _Pragma("unroll") \
            for (int i_ = 0; i_ < 2; i_++) { \
                int c_ = ac0 + i_; \
                cp16(ad_ + (uint32_t)((c_ ^ arx) << 4), ap_ + c_*8, ssz_); \
            } \
        } \
        { \
            const __half* bp_ = Wp + ((matBase + tap_)*128 + br)*128 + c0_; \
            uint32_t bd_ = base_ + 8192u + (uint32_t)br*128u; \
            _Pragma("unroll") \
            for (int i_ = 0; i_ < 4; i_++) { \
                int c_ = bh*4 + i_; \
                cp16(bd_ + (uint32_t)((c_ ^ brx) << 4), bp_ + c_*8, 16u); \
            } \
        } \
        cp_commit(); \
    } while (0)

    // prologue: stages 0..PD-2
#pragma unroll
    for (int s = 0; s < PD - 1; s++) LOAD_STAGE(s, s);

    int sbuf = 0;
    for (int s = 0; s < T; s++) {
        if (s + PD - 1 < T) CP_WAIT(PD - 2); else CP_WAIT(0);
        __syncthreads();
        if (s + PD - 1 < T) {
            int bufn = sbuf + PD - 1; if (bufn >= PD) bufn -= PD;
            LOAD_STAGE(s + PD - 1, bufn);
        }
        uint32_t stg = smS + (uint32_t)sbuf*STG_SZ;
#pragma unroll
        for (int ks = 0; ks < 4; ks++) {
            int cA = ks*2 + laneAc, cB = ks*2 + laneBc;
            uint32_t a[2][4], b[2][4];
            ldsm4(a[0], stg + offA[0] + (uint32_t)((cA ^ rxA[0]) << 4));
            ldsm4(a[1], stg + offA[1] + (uint32_t)((cA ^ rxA[1]) << 4));
            ldsm4(b[0], stg + offB[0] + (uint32_t)((cB ^ rxB[0]) << 4));
            ldsm4(b[1], stg + offB[1] + (uint32_t)((cB ^ rxB[1]) << 4));
#pragma unroll
            for (int mt = 0; mt < 2; mt++)
#pragma unroll
                for (int nt = 0; nt < 4; nt++)
                    mma_f16(acc[mt][nt], a[mt], &b[nt >> 1][(nt & 1)*2]);
        }
        sbuf++; if (sbuf == PD) sbuf = 0;
    }
#undef LOAD_STAGE

    // ---- epilogue: register -> gmem, fused bias (+residual) ----
#pragma unroll
    for (int mt = 0; mt < 2; mt++) {
        int rl = wm*32 + mt*16 + (lane >> 2);
#pragma unroll
        for (int half = 0; half < 2; half++) {
            int row = rl + half*8;
            int orow, prow;
            if (ISC2) { orow = bx*TM + row; prow = orow >> 3; }
            else      { orow = (bx*TM + row)*8 + ko; prow = -1; }
#pragma unroll
            for (int nt = 0; nt < 4; nt++) {
                int col = wn*32 + nt*8 + (lane & 3)*2;
                float2 bb = *reinterpret_cast<const float2*>(bias + col);
                float vx = acc[mt][nt][half*2 + 0] + bb.x;
                float vy = acc[mt][nt][half*2 + 1] + bb.y;
                if (ISC2) {
                    float2 rr = *reinterpret_cast<const float2*>(feats + prow*CH + col);
                    vx += rr.x; vy += rr.y;
                    float2 o; o.x = vx; o.y = vy;
                    *reinterpret_cast<float2*>(dout + orow*CH + col) = o;
                } else {
                    store_h2(g_o1h + orow*CH + col, vx, vy);
                }
            }
        }
    }
}

// ================= launch =================
extern "C" void kernel_launch(void* const* d_in, const int* in_sizes, int n_in,
                              void* d_out, int out_size) {
    const float* feats  = (const float*)d_in[0];
    const float* gamma1 = (const float*)d_in[1];
    const float* beta1  = (const float*)d_in[2];
    const float* W1     = (const float*)d_in[3];
    const float* b1     = (const float*)d_in[4];
    const float* gamma2 = (const float*)d_in[5];
    const float* beta2  = (const float*)d_in[6];
    const float* W2     = (const float*)d_in[7];
    const float* b2     = (const float*)d_in[8];
    const int*   coords = (const int*)d_in[9];
    float* out = (float*)d_out;

    const int smem1 = 3*STG_SZ + 8*TM*4;     // 75776  (PD=3)
    const int smem2 = 2*STG_SZ + 27*TM*4;    // 56064  (PD=2)
    cudaFuncSetAttribute(k_convmma<8,3,false>, cudaFuncAttributeMaxDynamicSharedMemorySize, smem1);
    cudaFuncSetAttribute(k_convmma<27,2,true>, cudaFuncAttributeMaxDynamicSharedMemorySize, smem2);

    // (0) grid build
    k_grid<<<1, 1024>>>(coords);
    // (1) weight prep -> fp16 [mat][n][k]
    k_prepw<<<(91*CH*CH + 255)/256, 256>>>(W1, W2);
    // (2) GN1 fused stats+norm+SiLU -> g_h1 (fp16)
    k_gn1<<<32, 256>>>(feats, gamma1, beta1);
    // (3) conv1 (parent-level, aggregated taps) -> g_o1h (fp16)   [ncu-profiled slot]
    k_convmma<8,3,false><<<dim3(NP/TM, 8), 256, smem1>>>(coords, b1, nullptr, nullptr);
    // (4,5) GN2 stats two-phase (reads fp16 o1)
    k_stats1<<<dim3(32, 32), 256>>>(32);
    k_stats2<<<32, 32>>>(32);
    // (6) GN2 normalize + SiLU -> g_h2 (fp16)
    k_gnsilu2<<<(NF*32 + 255)/256, 256>>>(gamma2, beta2);
    // (7) conv2 (fine-level, 27 taps) + bias + residual -> out
    k_convmma<27,2,true><<<NF/TM, 256, smem2>>>(coords, b2, feats, out);
}

// round 16
// speedup vs baseline: 1.1406x; 1.0275x over previous
#include <cuda_runtime.h>
#include <cuda_fp16.h>
#include <cstdint>

#define RESP 32
#define RESF 64
#define NP   8192
#define NF   65536
#define CH   128
#define EPSV 1e-5f

// ---- scratch (device globals: allocation-free rule) ----
__device__ int    g_pg[RESP*RESP*RESP];
__device__ __half g_h1[NP*CH];
__device__ __half g_o1h[NF*CH];      // conv1 output, fp16
__device__ __half g_h2[NF*CH];
__device__ __half g_M1h[64*CH*CH];   // aggregated conv1 weights, [mat][n][k], fp16
__device__ __half g_W2h[27*CH*CH];   // conv2 weights, [mat][n][k], fp16
__device__ float  g_sum[32], g_sq[32];      // GN2 stats
__device__ float  g_ps[32][32], g_pq[32][32];

// ================= helpers =================
__device__ __forceinline__ uint32_t smem_u32(const void* p) {
    uint32_t a;
    asm("{ .reg .u64 t; cvta.to.shared.u64 t, %1; cvt.u32.u64 %0, t; }" : "=r"(a) : "l"(p));
    return a;
}
__device__ __forceinline__ void cp16(uint32_t dst, const void* src, uint32_t ssz) {
    asm volatile("cp.async.cg.shared.global [%0], [%1], 16, %2;" :: "r"(dst), "l"(src), "r"(ssz));
}
__device__ __forceinline__ void cp_commit() { asm volatile("cp.async.commit_group;"); }
#define CP_WAIT(n) asm volatile("cp.async.wait_group %0;" :: "n"(n) : "memory")

__device__ __forceinline__ void ldsm4(uint32_t* r, uint32_t addr) {
    asm volatile("ldmatrix.sync.aligned.m8n8.x4.shared.b16 {%0,%1,%2,%3}, [%4];"
        : "=r"(r[0]), "=r"(r[1]), "=r"(r[2]), "=r"(r[3]) : "r"(addr));
}
// m16n8k16 fp16 MMA, fp32 accumulate
__device__ __forceinline__ void mma_f16(float* d, const uint32_t* a, const uint32_t* b) {
    asm volatile("mma.sync.aligned.m16n8k16.row.col.f32.f16.f16.f32 "
        "{%0,%1,%2,%3}, {%4,%5,%6,%7}, {%8,%9}, {%0,%1,%2,%3};"
        : "+f"(d[0]), "+f"(d[1]), "+f"(d[2]), "+f"(d[3])
        : "r"(a[0]), "r"(a[1]), "r"(a[2]), "r"(a[3]), "r"(b[0]), "r"(b[1]));
}
__device__ __forceinline__ void store_h4(__half* dst, float x, float y, float z, float w) {
    __half2 p0 = __floats2half2_rn(x, y);
    __half2 p1 = __floats2half2_rn(z, w);
    uint2 u;
    u.x = *reinterpret_cast<uint32_t*>(&p0);
    u.y = *reinterpret_cast<uint32_t*>(&p1);
    *reinterpret_cast<uint2*>(dst) = u;
}
__device__ __forceinline__ void store_h2(__half* dst, float x, float y) {
    __half2 p = __floats2half2_rn(x, y);
    *reinterpret_cast<uint32_t*>(dst) = *reinterpret_cast<uint32_t*>(&p);
}

// ================= fused grid build =================
__global__ __launch_bounds__(1024)
void k_grid(const int* __restrict__ coords) {
    int t = threadIdx.x;
    for (int i = t; i < RESP*RESP*RESP; i += 1024) g_pg[i] = -1;
    __syncthreads();
    for (int i = t; i < NP; i += 1024)
        g_pg[(coords[i*3]*RESP + coords[i*3+1])*RESP + coords[i*3+2]] = i;
}

// ================= weight prep: conv1 aggregate (fp16, [mat][n][k]) =================
__global__ void k_prepM1(const float* __restrict__ W1) {
    int idx = blockIdx.x * blockDim.x + threadIdx.x;
    if (idx >= 64*CH*CH) return;
    int m = idx >> 14, rest = idx & 16383;
    int n = rest >> 7, kk = rest & 127;
    int k = m >> 3, j = m & 7;
    int s[3], cnt[3];
#pragma unroll
    for (int a = 0; a < 3; a++) {
        int o  = (k >> (2 - a)) & 1;
        int eb = (j >> (2 - a)) & 1;
        cnt[a] = 1 + (o ^ eb);
        s[a]   = -1 + eb * (1 + o);
    }
    float acc = 0.f;
    for (int d0 = 0; d0 < cnt[0]; d0++)
        for (int d1 = 0; d1 < cnt[1]; d1++)
            for (int d2 = 0; d2 < cnt[2]; d2++) {
                int k27 = ((s[0]+d0+1)*3 + (s[1]+d1+1))*3 + (s[2]+d2+1);
                acc += W1[k27*CH*CH + kk*CH + n];
            }
    g_M1h[idx] = __float2half_rn(acc);
}

// ================= weight prep: conv2 transpose (fp16, [mat][n][k]) =================
__global__ void k_prepW2(const float* __restrict__ W2) {
    int idx = blockIdx.x * blockDim.x + threadIdx.x;
    if (idx >= 27*CH*CH) return;
    int m = idx >> 14, rest = idx & 16383;
    int n = rest >> 7, kk = rest & 127;
    g_W2h[idx] = __float2half_rn(W2[m*CH*CH + kk*CH + n]);
}

// ================= GN1: fused stats + normalize + SiLU -> fp16 =================
__global__ __launch_bounds__(256)
void k_gn1(const float* __restrict__ feats,
           const float* __restrict__ gamma, const float* __restrict__ beta) {
    int g = blockIdx.x, t = threadIdx.x;
    float s = 0.f, q = 0.f;
    for (int r = t; r < NP; r += 256) {
        float4 v = *reinterpret_cast<const float4*>(feats + r*CH + g*4);
        s += (v.x + v.y) + (v.z + v.w);
        q += (v.x*v.x + v.y*v.y) + (v.z*v.z + v.w*v.w);
    }
    __shared__ float ss[256], sq[256];
    ss[t] = s; sq[t] = q;
    __syncthreads();
    for (int st = 128; st > 0; st >>= 1) {
        if (t < st) { ss[t] += ss[t+st]; sq[t] += sq[t+st]; }
        __syncthreads();
    }
    const float invcnt = 1.f / (NP * 4);
    float mean = ss[0] * invcnt;
    float var  = sq[0] * invcnt - mean * mean;
    float inv  = rsqrtf(var + EPSV);
    float4 ga = *reinterpret_cast<const float4*>(gamma + g*4);
    float4 be = *reinterpret_cast<const float4*>(beta + g*4);
    for (int r = t; r < NP; r += 256) {
        float4 v = *reinterpret_cast<const float4*>(feats + r*CH + g*4);
        float y, ox, oy, oz, ow;
        y = (v.x - mean)*inv*ga.x + be.x; ox = y / (1.f + expf(-y));
        y = (v.y - mean)*inv*ga.y + be.y; oy = y / (1.f + expf(-y));
        y = (v.z - mean)*inv*ga.z + be.z; oz = y / (1.f + expf(-y));
        y = (v.w - mean)*inv*ga.w + be.w; ow = y / (1.f + expf(-y));
        store_h4(g_h1 + r*CH + g*4, ox, oy, oz, ow);
    }
}

// ================= GN2 stats (two-phase over fp16 g_o1h) =================
__global__ void k_stats1(int nsl) {
    int g = blockIdx.x, sl = blockIdx.y;
    int per = NF / nsl, r0 = sl * per;
    float s = 0.f, q = 0.f;
    for (int r = r0 + threadIdx.x; r < r0 + per; r += blockDim.x) {
        uint2 u = *reinterpret_cast<const uint2*>(g_o1h + r*CH + g*4);
        float2 v0 = __half22float2(*reinterpret_cast<__half2*>(&u.x));
        float2 v1 = __half22float2(*reinterpret_cast<__half2*>(&u.y));
        s += (v0.x + v0.y) + (v1.x + v1.y);
        q += (v0.x*v0.x + v0.y*v0.y) + (v1.x*v1.x + v1.y*v1.y);
    }
    __shared__ float ss[256], sq[256];
    ss[threadIdx.x] = s; sq[threadIdx.x] = q;
    __syncthreads();
    for (int st = 128; st > 0; st >>= 1) {
        if (threadIdx.x < st) { ss[threadIdx.x] += ss[threadIdx.x+st]; sq[threadIdx.x] += sq[threadIdx.x+st]; }
        __syncthreads();
    }
    if (threadIdx.x == 0) { g_ps[g][sl] = ss[0]; g_pq[g][sl] = sq[0]; }
}
__global__ void k_stats2(int nsl) {
    int g = blockIdx.x, t = threadIdx.x;
    float s = (t < nsl) ? g_ps[g][t] : 0.f;
    float q = (t < nsl) ? g_pq[g][t] : 0.f;
#pragma unroll
    for (int o = 16; o > 0; o >>= 1) {
        s += __shfl_xor_sync(0xffffffff, s, o);
        q += __shfl_xor_sync(0xffffffff, q, o);
    }
    if (t == 0) { g_sum[g] = s; g_sq[g] = q; }
}
__global__ void k_gnsilu2(const float* __restrict__ gamma, const float* __restrict__ beta) {
    int idx = blockIdx.x * blockDim.x + threadIdx.x;
    if (idx >= NF*32) return;
    int g = idx & 31;
    const float invcnt = 1.f / (NF * 4);
    float mean = g_sum[g] * invcnt;
    float var  = g_sq[g] * invcnt - mean * mean;
    float inv  = rsqrtf(var + EPSV);
    uint2 u = *reinterpret_cast<const uint2*>(g_o1h + idx*4);
    float2 v0 = __half22float2(*reinterpret_cast<__half2*>(&u.x));
    float2 v1 = __half22float2(*reinterpret_cast<__half2*>(&u.y));
    float4 ga = reinterpret_cast<const float4*>(gamma)[g];
    float4 be = reinterpret_cast<const float4*>(beta)[g];
    float y, ox, oy, oz, ow;
    y = (v0.x - mean)*inv*ga.x + be.x; ox = y / (1.f + expf(-y));
    y = (v0.y - mean)*inv*ga.y + be.y; oy = y / (1.f + expf(-y));
    y = (v1.x - mean)*inv*ga.z + be.z; oz = y / (1.f + expf(-y));
    y = (v1.y - mean)*inv*ga.w + be.w; ow = y / (1.f + expf(-y));
    store_h4(g_h2 + idx*4, ox, oy, oz, ow);
}

// ================= fp16 mma conv kernels =================
// CTA 64 rows x 128 cols, 8 warps (2m x 4n), warp tile 32x32 -> acc=32 regs.
// BK=64 fp16 per stage; stage = A 8KB + B 16KB = 24KB. PD-stage cp.async.
// __launch_bounds__(256,3): 3 CTAs/SM = 24 warps.
#define STG_SZ 24576
#define TM 64

template<int NTAPS, int PD, bool ISC2>
__global__ __launch_bounds__(256, 3)
void k_convmma(const int* __restrict__ coords, const float* __restrict__ bias,
               const float* __restrict__ feats, float* __restrict__ dout) {
    extern __shared__ char dsm[];
    uint32_t smS = smem_u32(dsm);
    int* snb = (int*)(dsm + PD*STG_SZ);

    const __half* hsrc = ISC2 ? g_h2  : g_h1;
    const __half* Wp   = ISC2 ? g_W2h : g_M1h;

    int tid = threadIdx.x, lane = tid & 31, wid = tid >> 5;
    int wm = wid >> 2, wn = wid & 3;          // 2m x 4n
    int bx = blockIdx.x, ko = blockIdx.y;
    const int matBase = ISC2 ? 0 : ko*8;

    // ---- neighbor precompute (TM=64 rows) ----
    for (int t = tid; t < NTAPS*TM; t += 256) {
        int tap = t >> 6, row = t & (TM-1);
        int nb = -1;
        if (ISC2) {
            int grow = bx*TM + row;
            int pi = grow >> 3, k8 = grow & 7;
            int f0 = 2*coords[pi*3+0] + ((k8 >> 2) & 1) + (tap/9 - 1);
            int f1 = 2*coords[pi*3+1] + ((k8 >> 1) & 1) + ((tap/3) % 3 - 1);
            int f2 = 2*coords[pi*3+2] + (k8 & 1)        + (tap % 3 - 1);
            if ((unsigned)f0 < RESF && (unsigned)f1 < RESF && (unsigned)f2 < RESF) {
                int p = g_pg[((f0 >> 1)*RESP + (f1 >> 1))*RESP + (f2 >> 1)];
                if (p >= 0) nb = p*8 + (((f0 & 1) << 2) | ((f1 & 1) << 1) | (f2 & 1));
            }
        } else {
            int p = bx*TM + row;
            int q0 = coords[p*3+0] + ((ko >> 2) & 1) - 1 + ((tap >> 2) & 1);
            int q1 = coords[p*3+1] + ((ko >> 1) & 1) - 1 + ((tap >> 1) & 1);
            int q2 = coords[p*3+2] + (ko & 1)        - 1 + (tap & 1);
            if ((unsigned)q0 < RESP && (unsigned)q1 < RESP && (unsigned)q2 < RESP)
                nb = g_pg[(q0*RESP + q1)*RESP + q2];
        }
        snb[t] = nb;
    }
    __syncthreads();

    // loaders: A 64 rows -> 4 threads/row, 2 cp16 each; B 128 rows -> 2 threads/row, 4 cp16 each
    const int ar = tid >> 2, ac0 = (tid & 3) * 2, arx = ar & 7;
    const int br = tid >> 1, bh = tid & 1,       brx = br & 7;

    // ldsm lane constants (m16n8k16 fragment mapping)
    const int laneAr = (lane & 7) + ((lane >> 3) & 1)*8;
    const int laneAc = (lane >> 4) & 1;
    const int laneBr = (lane & 7) + ((lane >> 4) & 1)*8;
    const int laneBc = (lane >> 3) & 1;
    uint32_t offA[2], offB[2]; int rxA[2], rxB[2];
#pragma unroll
    for (int i = 0; i < 2; i++) {
        int rA = wm*32 + i*16 + laneAr;
        offA[i] = (uint32_t)rA * 128u; rxA[i] = rA & 7;
        int rB = wn*32 + i*16 + laneBr;
        offB[i] = 8192u + (uint32_t)rB * 128u; rxB[i] = rB & 7;
    }

    float acc[2][4][4];
#pragma unroll
    for (int mt = 0; mt < 2; mt++)
#pragma unroll
        for (int nt = 0; nt < 4; nt++)
#pragma unroll
            for (int c = 0; c < 4; c++) acc[mt][nt][c] = 0.f;

    const int T = NTAPS * 2;   // BK=64: 2 stages per tap

#define LOAD_STAGE(S, BUF) do { \
        int tap_ = (S) >> 1, c0_ = ((S) & 1) * 64; \
        uint32_t base_ = smS + (BUF)*STG_SZ; \
        { \
            int src_ = snb[tap_*TM + ar]; \
            uint32_t ssz_ = src_ >= 0 ? 16u : 0u; \
            const __half* ap_ = hsrc + (src_ < 0 ? 0 : src_)*CH + c0_; \
            uint32_t ad_ = base_ + (uint32_t)ar*128u; \
            _Pragma("unroll") \
            for (int i_ = 0; i_ < 2; i_++) { \
                int c_ = ac0 + i_; \
                cp16(ad_ + (uint32_t)((c_ ^ arx) << 4), ap_ + c_*8, ssz_); \
            } \
        } \
        { \
            const __half* bp_ = Wp + ((matBase + tap_)*128 + br)*128 + c0_; \
            uint32_t bd_ = base_ + 8192u + (uint32_t)br*128u; \
            _Pragma("unroll") \
            for (int i_ = 0; i_ < 4; i_++) { \
                int c_ = bh*4 + i_; \
                cp16(bd_ + (uint32_t)((c_ ^ brx) << 4), bp_ + c_*8, 16u); \
            } \
        } \
        cp_commit(); \
    } while (0)

    // prologue: stages 0..PD-2
#pragma unroll
    for (int s = 0; s < PD - 1; s++) LOAD_STAGE(s, s);

    int sbuf = 0;
    for (int s = 0; s < T; s++) {
        if (s + PD - 1 < T) CP_WAIT(PD - 2); else CP_WAIT(0);
        __syncthreads();
        if (s + PD - 1 < T) {
            int bufn = sbuf + PD - 1; if (bufn >= PD) bufn -= PD;
            LOAD_STAGE(s + PD - 1, bufn);
        }
        uint32_t stg = smS + (uint32_t)sbuf*STG_SZ;
#pragma unroll
        for (int ks = 0; ks < 4; ks++) {
            int cA = ks*2 + laneAc, cB = ks*2 + laneBc;
            uint32_t a[2][4], b[2][4];
            ldsm4(a[0], stg + offA[0] + (uint32_t)((cA ^ rxA[0]) << 4));
            ldsm4(a[1], stg + offA[1] + (uint32_t)((cA ^ rxA[1]) << 4));
            ldsm4(b[0], stg + offB[0] + (uint32_t)((cB ^ rxB[0]) << 4));
            ldsm4(b[1], stg + offB[1] + (uint32_t)((cB ^ rxB[1]) << 4));
#pragma unroll
            for (int mt = 0; mt < 2; mt++)
#pragma unroll
                for (int nt = 0; nt < 4; nt++)
                    mma_f16(acc[mt][nt], a[mt], &b[nt >> 1][(nt & 1)*2]);
        }
        sbuf++; if (sbuf == PD) sbuf = 0;
    }
#undef LOAD_STAGE

    // ---- epilogue: register -> gmem, fused bias (+residual) ----
#pragma unroll
    for (int mt = 0; mt < 2; mt++) {
        int rl = wm*32 + mt*16 + (lane >> 2);
#pragma unroll
        for (int half = 0; half < 2; half++) {
            int row = rl + half*8;
            int orow, prow;
            if (ISC2) { orow = bx*TM + row; prow = orow >> 3; }
            else      { orow = (bx*TM + row)*8 + ko; prow = -1; }
#pragma unroll
            for (int nt = 0; nt < 4; nt++) {
                int col = wn*32 + nt*8 + (lane & 3)*2;
                float2 bb = *reinterpret_cast<const float2*>(bias + col);
                float vx = acc[mt][nt][half*2 + 0] + bb.x;
                float vy = acc[mt][nt][half*2 + 1] + bb.y;
                if (ISC2) {
                    float2 rr = *reinterpret_cast<const float2*>(feats + prow*CH + col);
                    vx += rr.x; vy += rr.y;
                    float2 o; o.x = vx; o.y = vy;
                    *reinterpret_cast<float2*>(dout + orow*CH + col) = o;
                } else {
                    store_h2(g_o1h + orow*CH + col, vx, vy);
                }
            }
        }
    }
}

// ================= stream/event setup (created once, outside capture) =================
struct AuxStreams {
    cudaStream_t s1, s2;
    cudaEvent_t  e0, eM1, eGn1, eW2;
    AuxStreams() {
        cudaStreamCreateWithFlags(&s1, cudaStreamNonBlocking);
        cudaStreamCreateWithFlags(&s2, cudaStreamNonBlocking);
        cudaEventCreateWithFlags(&e0,   cudaEventDisableTiming);
        cudaEventCreateWithFlags(&eM1,  cudaEventDisableTiming);
        cudaEventCreateWithFlags(&eGn1, cudaEventDisableTiming);
        cudaEventCreateWithFlags(&eW2,  cudaEventDisableTiming);
    }
};

// ================= launch =================
extern "C" void kernel_launch(void* const* d_in, const int* in_sizes, int n_in,
                              void* d_out, int out_size) {
    const float* feats  = (const float*)d_in[0];
    const float* gamma1 = (const float*)d_in[1];
    const float* beta1  = (const float*)d_in[2];
    const float* W1     = (const float*)d_in[3];
    const float* b1     = (const float*)d_in[4];
    const float* gamma2 = (const float*)d_in[5];
    const float* beta2  = (const float*)d_in[6];
    const float* W2     = (const float*)d_in[7];
    const float* b2     = (const float*)d_in[8];
    const int*   coords = (const int*)d_in[9];
    float* out = (float*)d_out;

    static AuxStreams aux;   // constructed on first (uncaptured) call

    const int smem1 = 3*STG_SZ + 8*TM*4;     // 75776  (PD=3)
    const int smem2 = 2*STG_SZ + 27*TM*4;    // 56064  (PD=2)
    cudaFuncSetAttribute(k_convmma<8,3,false>, cudaFuncAttributeMaxDynamicSharedMemorySize, smem1);
    cudaFuncSetAttribute(k_convmma<27,2,true>, cudaFuncAttributeMaxDynamicSharedMemorySize, smem2);

    // ---- fork: grid (main) || prepM1->prepW2 (s1) || gn1 (s2) ----
    cudaEventRecord(aux.e0, 0);
    cudaStreamWaitEvent(aux.s1, aux.e0, 0);
    cudaStreamWaitEvent(aux.s2, aux.e0, 0);

    k_grid<<<1, 1024>>>(coords);                                   // main stream
    k_prepM1<<<(64*CH*CH + 255)/256, 256, 0, aux.s1>>>(W1);        // s1
    cudaEventRecord(aux.eM1, aux.s1);
    k_prepW2<<<(27*CH*CH + 255)/256, 256, 0, aux.s1>>>(W2);        // s1 (overlaps conv1)
    cudaEventRecord(aux.eW2, aux.s1);
    k_gn1<<<32, 256, 0, aux.s2>>>(feats, gamma1, beta1);           // s2
    cudaEventRecord(aux.eGn1, aux.s2);

    // ---- join for conv1: needs grid (main order) + M1 + gn1 ----
    cudaStreamWaitEvent(0, aux.eM1, 0);
    cudaStreamWaitEvent(0, aux.eGn1, 0);

    // conv1 (parent-level, aggregated taps) -> g_o1h (fp16)
    k_convmma<8,3,false><<<dim3(NP/TM, 8), 256, smem1>>>(coords, b1, nullptr, nullptr);
    // GN2 stats two-phase (reads fp16 o1)
    k_stats1<<<dim3(32, 32), 256>>>(32);
    k_stats2<<<32, 32>>>(32);
    // GN2 normalize + SiLU -> g_h2 (fp16)
    k_gnsilu2<<<(NF*32 + 255)/256, 256>>>(gamma2, beta2);

    // ---- join for conv2: needs W2 prep (ran concurrent with conv1 chain) ----
    cudaStreamWaitEvent(0, aux.eW2, 0);

    // conv2 (fine-level, 27 taps) + bias + residual -> out
    k_convmma<27,2,true><<<NF/TM, 256, smem2>>>(coords, b2, feats, out);
}

// round 17
// speedup vs baseline: 1.1971x; 1.0495x over previous
#include <cuda_runtime.h>
#include <cuda_fp16.h>
#include <cstdint>

#define RESP 32
#define RESF 64
#define NP   8192
#define NF   65536
#define CH   128
#define EPSV 1e-5f

// ---- scratch (device globals: allocation-free rule) ----
__device__ int    g_pg[RESP*RESP*RESP];
__device__ __half g_h1[NP*CH];
__device__ __half g_o1h[NF*CH];      // conv1 output, fp16
__device__ __half g_h2[NF*CH];
__device__ __half g_M1h[64*CH*CH];   // aggregated conv1 weights, [mat][n][k], fp16
__device__ __half g_W2h[27*CH*CH];   // conv2 weights, [mat][n][k], fp16
__device__ float  g_sum[32], g_sq[32];      // GN2 stats
__device__ float  g_sum1[32], g_sq1[32];    // GN1 stats
__device__ float  g_ps[32][32], g_pq[32][32];     // GN2 partials
__device__ float  g_ps1[32][8], g_pq1[32][8];     // GN1 partials

// ================= helpers =================
__device__ __forceinline__ uint32_t smem_u32(const void* p) {
    uint32_t a;
    asm("{ .reg .u64 t; cvta.to.shared.u64 t, %1; cvt.u32.u64 %0, t; }" : "=r"(a) : "l"(p));
    return a;
}
__device__ __forceinline__ void cp16(uint32_t dst, const void* src, uint32_t ssz) {
    asm volatile("cp.async.cg.shared.global [%0], [%1], 16, %2;" :: "r"(dst), "l"(src), "r"(ssz));
}
__device__ __forceinline__ void cp_commit() { asm volatile("cp.async.commit_group;"); }
#define CP_WAIT(n) asm volatile("cp.async.wait_group %0;" :: "n"(n) : "memory")

__device__ __forceinline__ void ldsm4(uint32_t* r, uint32_t addr) {
    asm volatile("ldmatrix.sync.aligned.m8n8.x4.shared.b16 {%0,%1,%2,%3}, [%4];"
        : "=r"(r[0]), "=r"(r[1]), "=r"(r[2]), "=r"(r[3]) : "r"(addr));
}
// m16n8k16 fp16 MMA, fp32 accumulate
__device__ __forceinline__ void mma_f16(float* d, const uint32_t* a, const uint32_t* b) {
    asm volatile("mma.sync.aligned.m16n8k16.row.col.f32.f16.f16.f32 "
        "{%0,%1,%2,%3}, {%4,%5,%6,%7}, {%8,%9}, {%0,%1,%2,%3};"
        : "+f"(d[0]), "+f"(d[1]), "+f"(d[2]), "+f"(d[3])
        : "r"(a[0]), "r"(a[1]), "r"(a[2]), "r"(a[3]), "r"(b[0]), "r"(b[1]));
}
__device__ __forceinline__ void store_h4(__half* dst, float x, float y, float z, float w) {
    __half2 p0 = __floats2half2_rn(x, y);
    __half2 p1 = __floats2half2_rn(z, w);
    uint2 u;
    u.x = *reinterpret_cast<uint32_t*>(&p0);
    u.y = *reinterpret_cast<uint32_t*>(&p1);
    *reinterpret_cast<uint2*>(dst) = u;
}
__device__ __forceinline__ void store_h2(__half* dst, float x, float y) {
    __half2 p = __floats2half2_rn(x, y);
    *reinterpret_cast<uint32_t*>(dst) = *reinterpret_cast<uint32_t*>(&p);
}

// ================= fused grid build =================
__global__ __launch_bounds__(1024)
void k_grid(const int* __restrict__ coords) {
    int t = threadIdx.x;
    for (int i = t; i < RESP*RESP*RESP; i += 1024) g_pg[i] = -1;
    __syncthreads();
    for (int i = t; i < NP; i += 1024)
        g_pg[(coords[i*3]*RESP + coords[i*3+1])*RESP + coords[i*3+2]] = i;
}

// ================= weight prep: conv1 aggregate (fp16, [mat][n][k]) =================
__global__ void k_prepM1(const float* __restrict__ W1) {
    int idx = blockIdx.x * blockDim.x + threadIdx.x;
    if (idx >= 64*CH*CH) return;
    int m = idx >> 14, rest = idx & 16383;
    int n = rest >> 7, kk = rest & 127;
    int k = m >> 3, j = m & 7;
    int s[3], cnt[3];
#pragma unroll
    for (int a = 0; a < 3; a++) {
        int o  = (k >> (2 - a)) & 1;
        int eb = (j >> (2 - a)) & 1;
        cnt[a] = 1 + (o ^ eb);
        s[a]   = -1 + eb * (1 + o);
    }
    float acc = 0.f;
    for (int d0 = 0; d0 < cnt[0]; d0++)
        for (int d1 = 0; d1 < cnt[1]; d1++)
            for (int d2 = 0; d2 < cnt[2]; d2++) {
                int k27 = ((s[0]+d0+1)*3 + (s[1]+d1+1))*3 + (s[2]+d2+1);
                acc += W1[k27*CH*CH + kk*CH + n];
            }
    g_M1h[idx] = __float2half_rn(acc);
}

// ================= weight prep: conv2 transpose (fp16, [mat][n][k]) =================
__global__ void k_prepW2(const float* __restrict__ W2) {
    int idx = blockIdx.x * blockDim.x + threadIdx.x;
    if (idx >= 27*CH*CH) return;
    int m = idx >> 14, rest = idx & 16383;
    int n = rest >> 7, kk = rest & 127;
    g_W2h[idx] = __float2half_rn(W2[m*CH*CH + kk*CH + n]);
}

// ================= GN1: two-phase stats + wide normalize =================
__global__ void k_g1stats(const float* __restrict__ feats) {
    int g = blockIdx.x, sl = blockIdx.y;          // 32 groups x 8 slices
    int per = NP / 8, r0 = sl * per;
    float s = 0.f, q = 0.f;
    for (int r = r0 + threadIdx.x; r < r0 + per; r += blockDim.x) {
        float4 v = *reinterpret_cast<const float4*>(feats + r*CH + g*4);
        s += (v.x + v.y) + (v.z + v.w);
        q += (v.x*v.x + v.y*v.y) + (v.z*v.z + v.w*v.w);
    }
    __shared__ float ss[256], sq[256];
    ss[threadIdx.x] = s; sq[threadIdx.x] = q;
    __syncthreads();
    for (int st = 128; st > 0; st >>= 1) {
        if (threadIdx.x < st) { ss[threadIdx.x] += ss[threadIdx.x+st]; sq[threadIdx.x] += sq[threadIdx.x+st]; }
        __syncthreads();
    }
    if (threadIdx.x == 0) { g_ps1[g][sl] = ss[0]; g_pq1[g][sl] = sq[0]; }
}
__global__ void k_g1stats2() {
    int g = blockIdx.x, t = threadIdx.x;
    float s = (t < 8) ? g_ps1[g][t] : 0.f;
    float q = (t < 8) ? g_pq1[g][t] : 0.f;
#pragma unroll
    for (int o = 4; o > 0; o >>= 1) {
        s += __shfl_xor_sync(0xffffffff, s, o);
        q += __shfl_xor_sync(0xffffffff, q, o);
    }
    if (t == 0) { g_sum1[g] = s; g_sq1[g] = q; }
}
__global__ void k_g1norm(const float* __restrict__ feats,
                         const float* __restrict__ gamma, const float* __restrict__ beta) {
    int idx = blockIdx.x * blockDim.x + threadIdx.x;
    if (idx >= NP*32) return;
    int g = idx & 31;
    const float invcnt = 1.f / (NP * 4);
    float mean = g_sum1[g] * invcnt;
    float var  = g_sq1[g] * invcnt - mean * mean;
    float inv  = rsqrtf(var + EPSV);
    float4 v  = reinterpret_cast<const float4*>(feats)[idx];
    float4 ga = reinterpret_cast<const float4*>(gamma)[g];
    float4 be = reinterpret_cast<const float4*>(beta)[g];
    float y, ox, oy, oz, ow;
    y = (v.x - mean)*inv*ga.x + be.x; ox = y / (1.f + expf(-y));
    y = (v.y - mean)*inv*ga.y + be.y; oy = y / (1.f + expf(-y));
    y = (v.z - mean)*inv*ga.z + be.z; oz = y / (1.f + expf(-y));
    y = (v.w - mean)*inv*ga.w + be.w; ow = y / (1.f + expf(-y));
    store_h4(g_h1 + idx*4, ox, oy, oz, ow);
}

// ================= GN2 stats (two-phase over fp16 g_o1h) =================
__global__ void k_stats1(int nsl) {
    int g = blockIdx.x, sl = blockIdx.y;
    int per = NF / nsl, r0 = sl * per;
    float s = 0.f, q = 0.f;
    for (int r = r0 + threadIdx.x; r < r0 + per; r += blockDim.x) {
        uint2 u = *reinterpret_cast<const uint2*>(g_o1h + r*CH + g*4);
        float2 v0 = __half22float2(*reinterpret_cast<__half2*>(&u.x));
        float2 v1 = __half22float2(*reinterpret_cast<__half2*>(&u.y));
        s += (v0.x + v0.y) + (v1.x + v1.y);
        q += (v0.x*v0.x + v0.y*v0.y) + (v1.x*v1.x + v1.y*v1.y);
    }
    __shared__ float ss[256], sq[256];
    ss[threadIdx.x] = s; sq[threadIdx.x] = q;
    __syncthreads();
    for (int st = 128; st > 0; st >>= 1) {
        if (threadIdx.x < st) { ss[threadIdx.x] += ss[threadIdx.x+st]; sq[threadIdx.x] += sq[threadIdx.x+st]; }
        __syncthreads();
    }
    if (threadIdx.x == 0) { g_ps[g][sl] = ss[0]; g_pq[g][sl] = sq[0]; }
}
__global__ void k_stats2(int nsl) {
    int g = blockIdx.x, t = threadIdx.x;
    float s = (t < nsl) ? g_ps[g][t] : 0.f;
    float q = (t < nsl) ? g_pq[g][t] : 0.f;
#pragma unroll
    for (int o = 16; o > 0; o >>= 1) {
        s += __shfl_xor_sync(0xffffffff, s, o);
        q += __shfl_xor_sync(0xffffffff, q, o);
    }
    if (t == 0) { g_sum[g] = s; g_sq[g] = q; }
}
__global__ void k_gnsilu2(const float* __restrict__ gamma, const float* __restrict__ beta) {
    int idx = blockIdx.x * blockDim.x + threadIdx.x;
    if (idx >= NF*32) return;
    int g = idx & 31;
    const float invcnt = 1.f / (NF * 4);
    float mean = g_sum[g] * invcnt;
    float var  = g_sq[g] * invcnt - mean * mean;
    float inv  = rsqrtf(var + EPSV);
    uint2 u = *reinterpret_cast<const uint2*>(g_o1h + idx*4);
    float2 v0 = __half22float2(*reinterpret_cast<__half2*>(&u.x));
    float2 v1 = __half22float2(*reinterpret_cast<__half2*>(&u.y));
    float4 ga = reinterpret_cast<const float4*>(gamma)[g];
    float4 be = reinterpret_cast<const float4*>(beta)[g];
    float y, ox, oy, oz, ow;
    y = (v0.x - mean)*inv*ga.x + be.x; ox = y / (1.f + expf(-y));
    y = (v0.y - mean)*inv*ga.y + be.y; oy = y / (1.f + expf(-y));
    y = (v1.x - mean)*inv*ga.z + be.z; oz = y / (1.f + expf(-y));
    y = (v1.y - mean)*inv*ga.w + be.w; ow = y / (1.f + expf(-y));
    store_h4(g_h2 + idx*4, ox, oy, oz, ow);
}

// ================= fp16 mma conv kernels =================
// CTA 64 rows x 128 cols, 8 warps (2m x 4n), warp tile 32x32 -> acc=32 regs.
// BK=64 fp16 per stage; stage = A 8KB + B 16KB = 24KB. PD-stage cp.async.
// __launch_bounds__(256,3): 3 CTAs/SM = 24 warps.
#define STG_SZ 24576
#define TM 64

template<int NTAPS, int PD, bool ISC2>
__global__ __launch_bounds__(256, 3)
void k_convmma(const int* __restrict__ coords, const float* __restrict__ bias,
               const float* __restrict__ feats, float* __restrict__ dout) {
    extern __shared__ char dsm[];
    uint32_t smS = smem_u32(dsm);
    int* snb = (int*)(dsm + PD*STG_SZ);

    const __half* hsrc = ISC2 ? g_h2  : g_h1;
    const __half* Wp   = ISC2 ? g_W2h : g_M1h;

    int tid = threadIdx.x, lane = tid & 31, wid = tid >> 5;
    int wm = wid >> 2, wn = wid & 3;          // 2m x 4n
    int bx = blockIdx.x, ko = blockIdx.y;
    const int matBase = ISC2 ? 0 : ko*8;

    // ---- neighbor precompute (TM=64 rows) ----
    for (int t = tid; t < NTAPS*TM; t += 256) {
        int tap = t >> 6, row = t & (TM-1);
        int nb = -1;
        if (ISC2) {
            int grow = bx*TM + row;
            int pi = grow >> 3, k8 = grow & 7;
            int f0 = 2*coords[pi*3+0] + ((k8 >> 2) & 1) + (tap/9 - 1);
            int f1 = 2*coords[pi*3+1] + ((k8 >> 1) & 1) + ((tap/3) % 3 - 1);
            int f2 = 2*coords[pi*3+2] + (k8 & 1)        + (tap % 3 - 1);
            if ((unsigned)f0 < RESF && (unsigned)f1 < RESF && (unsigned)f2 < RESF) {
                int p = g_pg[((f0 >> 1)*RESP + (f1 >> 1))*RESP + (f2 >> 1)];
                if (p >= 0) nb = p*8 + (((f0 & 1) << 2) | ((f1 & 1) << 1) | (f2 & 1));
            }
        } else {
            int p = bx*TM + row;
            int q0 = coords[p*3+0] + ((ko >> 2) & 1) - 1 + ((tap >> 2) & 1);
            int q1 = coords[p*3+1] + ((ko >> 1) & 1) - 1 + ((tap >> 1) & 1);
            int q2 = coords[p*3+2] + (ko & 1)        - 1 + (tap & 1);
            if ((unsigned)q0 < RESP && (unsigned)q1 < RESP && (unsigned)q2 < RESP)
                nb = g_pg[(q0*RESP + q1)*RESP + q2];
        }
        snb[t] = nb;
    }
    __syncthreads();

    // loaders: A 64 rows -> 4 threads/row, 2 cp16 each; B 128 rows -> 2 threads/row, 4 cp16 each
    const int ar = tid >> 2, ac0 = (tid & 3) * 2, arx = ar & 7;
    const int br = tid >> 1, bh = tid & 1,       brx = br & 7;

    // ldsm lane constants (m16n8k16 fragment mapping)
    const int laneAr = (lane & 7) + ((lane >> 3) & 1)*8;
    const int laneAc = (lane >> 4) & 1;
    const int laneBr = (lane & 7) + ((lane >> 4) & 1)*8;
    const int laneBc = (lane >> 3) & 1;
    uint32_t offA[2], offB[2]; int rxA[2], rxB[2];
#pragma unroll
    for (int i = 0; i < 2; i++) {
        int rA = wm*32 + i*16 + laneAr;
        offA[i] = (uint32_t)rA * 128u; rxA[i] = rA & 7;
        int rB = wn*32 + i*16 + laneBr;
        offB[i] = 8192u + (uint32_t)rB * 128u; rxB[i] = rB & 7;
    }

    float acc[2][4][4];
#pragma unroll
    for (int mt = 0; mt < 2; mt++)
#pragma unroll
        for (int nt = 0; nt < 4; nt++)
#pragma unroll
            for (int c = 0; c < 4; c++) acc[mt][nt][c] = 0.f;

    const int T = NTAPS * 2;   // BK=64: 2 stages per tap

#define LOAD_STAGE(S, BUF) do { \
        int tap_ = (S) >> 1, c0_ = ((S) & 1) * 64; \
        uint32_t base_ = smS + (BUF)*STG_SZ; \
        { \
            int src_ = snb[tap_*TM + ar]; \
            uint32_t ssz_ = src_ >= 0 ? 16u : 0u; \
            const __half* ap_ = hsrc + (src_ < 0 ? 0 : src_)*CH + c0_; \
            uint32_t ad_ = base_ + (uint32_t)ar*128u; \
            _Pragma("unroll") \
            for (int i_ = 0; i_ < 2; i_++) { \
                int c_ = ac0 + i_; \
                cp16(ad_ + (uint32_t)((c_ ^ arx) << 4), ap_ + c_*8, ssz_); \
            } \
        } \
        { \
            const __half* bp_ = Wp + ((matBase + tap_)*128 + br)*128 + c0_; \
            uint32_t bd_ = base_ + 8192u + (uint32_t)br*128u; \
            _Pragma("unroll") \
            for (int i_ = 0; i_ < 4; i_++) { \
                int c_ = bh*4 + i_; \
                cp16(bd_ + (uint32_t)((c_ ^ brx) << 4), bp_ + c_*8, 16u); \
            } \
        } \
        cp_commit(); \
    } while (0)

    // prologue: stages 0..PD-2
#pragma unroll
    for (int s = 0; s < PD - 1; s++) LOAD_STAGE(s, s);

    int sbuf = 0;
    for (int s = 0; s < T; s++) {
        if (s + PD - 1 < T) CP_WAIT(PD - 2); else CP_WAIT(0);
        __syncthreads();
        if (s + PD - 1 < T) {
            int bufn = sbuf + PD - 1; if (bufn >= PD) bufn -= PD;
            LOAD_STAGE(s + PD - 1, bufn);
        }
        uint32_t stg = smS + (uint32_t)sbuf*STG_SZ;
#pragma unroll
        for (int ks = 0; ks < 4; ks++) {
            int cA = ks*2 + laneAc, cB = ks*2 + laneBc;
            uint32_t a[2][4], b[2][4];
            ldsm4(a[0], stg + offA[0] + (uint32_t)((cA ^ rxA[0]) << 4));
            ldsm4(a[1], stg + offA[1] + (uint32_t)((cA ^ rxA[1]) << 4));
            ldsm4(b[0], stg + offB[0] + (uint32_t)((cB ^ rxB[0]) << 4));
            ldsm4(b[1], stg + offB[1] + (uint32_t)((cB ^ rxB[1]) << 4));
#pragma unroll
            for (int mt = 0; mt < 2; mt++)
#pragma unroll
                for (int nt = 0; nt < 4; nt++)
                    mma_f16(acc[mt][nt], a[mt], &b[nt >> 1][(nt & 1)*2]);
        }
        sbuf++; if (sbuf == PD) sbuf = 0;
    }
#undef LOAD_STAGE

    // ---- epilogue: register -> gmem, fused bias (+residual) ----
#pragma unroll
    for (int mt = 0; mt < 2; mt++) {
        int rl = wm*32 + mt*16 + (lane >> 2);
#pragma unroll
        for (int half = 0; half < 2; half++) {
            int row = rl + half*8;
            int orow, prow;
            if (ISC2) { orow = bx*TM + row; prow = orow >> 3; }
            else      { orow = (bx*TM + row)*8 + ko; prow = -1; }
#pragma unroll
            for (int nt = 0; nt < 4; nt++) {
                int col = wn*32 + nt*8 + (lane & 3)*2;
                float2 bb = *reinterpret_cast<const float2*>(bias + col);
                float vx = acc[mt][nt][half*2 + 0] + bb.x;
                float vy = acc[mt][nt][half*2 + 1] + bb.y;
                if (ISC2) {
                    float2 rr = *reinterpret_cast<const float2*>(feats + prow*CH + col);
                    vx += rr.x; vy += rr.y;
                    float2 o; o.x = vx; o.y = vy;
                    *reinterpret_cast<float2*>(dout + orow*CH + col) = o;
                } else {
                    store_h2(g_o1h + orow*CH + col, vx, vy);
                }
            }
        }
    }
}

// ================= stream/event setup (created once, outside capture) =================
struct AuxStreams {
    cudaStream_t s1, s2;
    cudaEvent_t  e0, eM1, eGn1, eW2;
    AuxStreams() {
        cudaStreamCreateWithFlags(&s1, cudaStreamNonBlocking);
        cudaStreamCreateWithFlags(&s2, cudaStreamNonBlocking);
        cudaEventCreateWithFlags(&e0,   cudaEventDisableTiming);
        cudaEventCreateWithFlags(&eM1,  cudaEventDisableTiming);
        cudaEventCreateWithFlags(&eGn1, cudaEventDisableTiming);
        cudaEventCreateWithFlags(&eW2,  cudaEventDisableTiming);
    }
};

// ================= launch =================
extern "C" void kernel_launch(void* const* d_in, const int* in_sizes, int n_in,
                              void* d_out, int out_size) {
    const float* feats  = (const float*)d_in[0];
    const float* gamma1 = (const float*)d_in[1];
    const float* beta1  = (const float*)d_in[2];
    const float* W1     = (const float*)d_in[3];
    const float* b1     = (const float*)d_in[4];
    const float* gamma2 = (const float*)d_in[5];
    const float* beta2  = (const float*)d_in[6];
    const float* W2     = (const float*)d_in[7];
    const float* b2     = (const float*)d_in[8];
    const int*   coords = (const int*)d_in[9];
    float* out = (float*)d_out;

    static AuxStreams aux;   // constructed on first (uncaptured) call

    const int smem1 = 3*STG_SZ + 8*TM*4;     // 75776  (PD=3)
    const int smem2 = 2*STG_SZ + 27*TM*4;    // 56064  (PD=2)
    cudaFuncSetAttribute(k_convmma<8,3,false>, cudaFuncAttributeMaxDynamicSharedMemorySize, smem1);
    cudaFuncSetAttribute(k_convmma<27,2,true>, cudaFuncAttributeMaxDynamicSharedMemorySize, smem2);

    // ---- fork: grid (main) || prepM1->prepW2 (s1) || gn1 3-phase (s2) ----
    cudaEventRecord(aux.e0, 0);
    cudaStreamWaitEvent(aux.s1, aux.e0, 0);
    cudaStreamWaitEvent(aux.s2, aux.e0, 0);

    k_grid<<<1, 1024>>>(coords);                                   // main stream
    k_prepM1<<<(64*CH*CH + 255)/256, 256, 0, aux.s1>>>(W1);        // s1
    cudaEventRecord(aux.eM1, aux.s1);
    k_prepW2<<<(27*CH*CH + 255)/256, 256, 0, aux.s1>>>(W2);        // s1 (overlaps conv1)
    cudaEventRecord(aux.eW2, aux.s1);
    k_g1stats<<<dim3(32, 8), 256, 0, aux.s2>>>(feats);             // s2
    k_g1stats2<<<32, 32, 0, aux.s2>>>();
    k_g1norm<<<(NP*32 + 255)/256, 256, 0, aux.s2>>>(feats, gamma1, beta1);
    cudaEventRecord(aux.eGn1, aux.s2);

    // ---- join for conv1: needs grid (main order) + M1 + gn1 ----
    cudaStreamWaitEvent(0, aux.eM1, 0);
    cudaStreamWaitEvent(0, aux.eGn1, 0);

    // conv1 (parent-level, aggregated taps) -> g_o1h (fp16)
    k_convmma<8,3,false><<<dim3(NP/TM, 8), 256, smem1>>>(coords, b1, nullptr, nullptr);
    // GN2 stats two-phase (reads fp16 o1)
    k_stats1<<<dim3(32, 32), 256>>>(32);
    k_stats2<<<32, 32>>>(32);
    // GN2 normalize + SiLU -> g_h2 (fp16)
    k_gnsilu2<<<(NF*32 + 255)/256, 256>>>(gamma2, beta2);

    // ---- join for conv2: needs W2 prep (ran concurrent with conv1 chain) ----
    cudaStreamWaitEvent(0, aux.eW2, 0);

    // conv2 (fine-level, 27 taps) + bias + residual -> out
    k_convmma<27,2,true><<<NF/TM, 256, smem2>>>(coords, b2, feats, out);
}